// round 1
// baseline (speedup 1.0000x reference)
#include <cuda_runtime.h>

typedef unsigned long long u64;

// ---- packed fp32x2 helpers (sm_100+; ptxas never emits these from C++) ----
static __device__ __forceinline__ u64 pack2(float x) {
    u64 r; asm("mov.b64 %0, {%1, %1};" : "=l"(r) : "f"(x)); return r;
}
static __device__ __forceinline__ u64 fma2(u64 a, u64 b, u64 c) {
    u64 d; asm("fma.rn.f32x2 %0, %1, %2, %3;" : "=l"(d) : "l"(a), "l"(b), "l"(c)); return d;
}

#define B_  2
#define H_  96
#define W_  128
#define D_  32
#define C_  16
#define F_  16
#define TW  8              // w-tile per CTA
#define NSLAB 30           // 3 h-rows x (TW+2) w
#define ROWS  17           // smem floats per depth row (16 + 1 pad)
#define SLABS 545          // 32*17 + 1 pad (breaks slab bank alignment)
#define IMG_PAD 16352      // NSLAB*SLABS=16350 rounded up to 16B multiple
#define WFL  (27*16*16)    // 6912 weight floats

extern __shared__ float smem[];

__global__ __launch_bounds__(128)
void sparse_conv3d_kernel(const float* __restrict__ images,
                          const int*   __restrict__ bp,
                          const float* __restrict__ kern,
                          const float* __restrict__ defv,
                          float*       __restrict__ out)
{
    float* s_img = smem;                    // [NSLAB][32][ROWS]
    float* s_w   = smem + IMG_PAD;          // [27][16][16]
    int*   s_bp  = (int*)(s_w + WFL);       // [NSLAB]

    const int tid = threadIdx.x;
    const int b   = blockIdx.z;
    const int h   = blockIdx.y;
    const int w0  = blockIdx.x * TW;

    // ---- stage weights (contiguous float4 copy) ----
    {
        const float4* src = (const float4*)kern;
        float4*       dst = (float4*)s_w;
        #pragma unroll
        for (int t = 0; t < WFL / 4; t += 128) {
            int idx = t + tid;
            if (idx < WFL / 4) dst[idx] = src[idx];
        }
    }

    // ---- stage base_plane for 3x10 neighborhood ----
    if (tid < NSLAB) {
        int r  = tid / 10, q = tid - r * 10;
        int hc = min(max(h + r - 1, 0), H_ - 1);
        int wc = min(max(w0 + q - 1, 0), W_ - 1);
        s_bp[tid] = bp[(b * H_ + hc) * W_ + wc];
    }

    // ---- stage 30 neighbor depth slabs (clamped; invalids masked later) ----
    {
        const int d  = tid >> 2;          // 0..31
        const int c4 = (tid & 3) << 2;    // 0,4,8,12
        int s = 0;
        #pragma unroll 1
        for (int r = 0; r < 3; ++r) {
            const int hc = min(max(h + r - 1, 0), H_ - 1);
            #pragma unroll 1
            for (int q = 0; q < 10; ++q, ++s) {
                const int wc = min(max(w0 + q - 1, 0), W_ - 1);
                const float4 v = *(const float4*)&images[
                    ((((size_t)b * H_ + hc) * W_ + wc) * D_ + d) * C_ + c4];
                float* p = s_img + s * SLABS + d * ROWS + c4;
                p[0] = v.x; p[1] = v.y; p[2] = v.z; p[3] = v.w;
            }
        }
    }
    __syncthreads();

    // ---- compute: thread = (w_local, depth pair {dp, dp+16}) ----
    const int wl = tid & 7;
    const int dp = tid >> 3;
    const int d0 = dp, d1 = dp + 16;
    const int w  = w0 + wl;
    const float dv = defv[0];
    const int bpc = s_bp[10 + wl + 1];    // center column's base plane

    u64 a0[8], a1[8];
    #pragma unroll
    for (int fp = 0; fp < 8; ++fp) { a0[fp] = 0ull; a1[fp] = 0ull; }

    #pragma unroll 1
    for (int i = 0; i < 3; ++i) {
        const int  hn = h + i - 1;
        const bool vh = (unsigned)hn < (unsigned)H_;
        #pragma unroll 1
        for (int j = 0; j < 3; ++j) {
            const int  wn  = w + j - 1;
            const bool spv = vh && ((unsigned)wn < (unsigned)W_);
            const int  s   = i * 10 + wl + j;
            const float* slab = s_img + s * SLABS;
            const int  rel = bpc - s_bp[s];
            const float* wt = s_w + (i * 3 + j) * 3 * 256;
            #pragma unroll
            for (int k = 0; k < 3; ++k) {
                const int dd0 = d0 + k - 1 + rel;
                const int dd1 = d1 + k - 1 + rel;
                const bool ok0 = spv && ((unsigned)dd0 < (unsigned)D_);
                const bool ok1 = spv && ((unsigned)dd1 < (unsigned)D_);
                const float* p0 = slab + min(max(dd0, 0), D_ - 1) * ROWS;
                const float* p1 = slab + min(max(dd1, 0), D_ - 1) * ROWS;
                const float* wk = wt + k * 256;
                #pragma unroll
                for (int c = 0; c < 16; ++c) {
                    const float x0 = ok0 ? p0[c] : dv;
                    const float x1 = ok1 ? p1[c] : dv;
                    const u64 A0 = pack2(x0);
                    const u64 A1 = pack2(x1);
                    const ulonglong2* wr = (const ulonglong2*)(wk + (c << 4));
                    ulonglong2 q01 = wr[0];
                    ulonglong2 q23 = wr[1];
                    ulonglong2 q45 = wr[2];
                    ulonglong2 q67 = wr[3];
                    a0[0] = fma2(A0, q01.x, a0[0]); a1[0] = fma2(A1, q01.x, a1[0]);
                    a0[1] = fma2(A0, q01.y, a0[1]); a1[1] = fma2(A1, q01.y, a1[1]);
                    a0[2] = fma2(A0, q23.x, a0[2]); a1[2] = fma2(A1, q23.x, a1[2]);
                    a0[3] = fma2(A0, q23.y, a0[3]); a1[3] = fma2(A1, q23.y, a1[3]);
                    a0[4] = fma2(A0, q45.x, a0[4]); a1[4] = fma2(A1, q45.x, a1[4]);
                    a0[5] = fma2(A0, q45.y, a0[5]); a1[5] = fma2(A1, q45.y, a1[5]);
                    a0[6] = fma2(A0, q67.x, a0[6]); a1[6] = fma2(A1, q67.x, a1[6]);
                    a0[7] = fma2(A0, q67.y, a0[7]); a1[7] = fma2(A1, q67.y, a1[7]);
                }
            }
        }
    }

    // ---- store: packed pairs are already (f, f+1) memory order ----
    const size_t ob = (((size_t)b * H_ + h) * W_ + w) * D_;
    {
        ulonglong2* o = (ulonglong2*)(out + (ob + d0) * F_);
        o[0] = make_ulonglong2(a0[0], a0[1]);
        o[1] = make_ulonglong2(a0[2], a0[3]);
        o[2] = make_ulonglong2(a0[4], a0[5]);
        o[3] = make_ulonglong2(a0[6], a0[7]);
    }
    {
        ulonglong2* o = (ulonglong2*)(out + (ob + d1) * F_);
        o[0] = make_ulonglong2(a1[0], a1[1]);
        o[1] = make_ulonglong2(a1[2], a1[3]);
        o[2] = make_ulonglong2(a1[4], a1[5]);
        o[3] = make_ulonglong2(a1[6], a1[7]);
    }
}

extern "C" void kernel_launch(void* const* d_in, const int* in_sizes, int n_in,
                              void* d_out, int out_size)
{
    // Identify inputs by element count (robust to metadata order):
    // images 2*96*128*32*16 = 12,582,912 | base_plane 24,576 | kernel 6,912 | default 1
    const float* images = nullptr;
    const int*   bp     = nullptr;
    const float* kern   = nullptr;
    const float* defv   = nullptr;
    for (int i = 0; i < n_in; ++i) {
        switch (in_sizes[i]) {
            case 12582912: images = (const float*)d_in[i]; break;
            case 24576:    bp     = (const int*)  d_in[i]; break;
            case 6912:     kern   = (const float*)d_in[i]; break;
            case 1:        defv   = (const float*)d_in[i]; break;
            default: break;
        }
    }
    // Positional fallback (setup_inputs order: images, base_plane, kernel, default)
    if (!images) images = (const float*)d_in[0];
    if (!bp)     bp     = (const int*)  d_in[1];
    if (!kern)   kern   = (const float*)d_in[2];
    if (!defv)   defv   = (const float*)d_in[3];

    const int smem_bytes = (IMG_PAD + WFL) * 4 + NSLAB * 4 + 8;
    cudaFuncSetAttribute(sparse_conv3d_kernel,
                         cudaFuncAttributeMaxDynamicSharedMemorySize, smem_bytes);

    dim3 grid(W_ / TW, H_, B_);   // (16, 96, 2)
    sparse_conv3d_kernel<<<grid, 128, smem_bytes>>>(
        images, bp, kern, defv, (float*)d_out);
}